// round 13
// baseline (speedup 1.0000x reference)
#include <cuda_runtime.h>
#include <cuda_bf16.h>
#include <cstddef>
#include <cstdint>

#define N_NODES 20000
#define N_EDGES 320000
#define N_GRAPHS 256
#define F_IN 128
#define HID 512
#define HCAT 2048   // 4*HID
#define USZ (HID * F_IN)

// ---------------- scratch (static device globals; no allocations) ----------
__device__ float g_deg[N_NODES];
__device__ float g_dis[N_NODES];
__device__ int   g_cnt[N_NODES];
__device__ int   g_rowstart[N_NODES + 1];
__device__ int   g_cursor[N_NODES];
__device__ int   g_csr_src[N_EDGES];
__device__ float g_csr_w[N_EDGES];
__device__ int   g_gcount[N_GRAPHS];
__device__ int   g_gstart[N_GRAPHS + 1];

__device__ float g_Pa[(size_t)N_NODES * F_IN];
__device__ float g_Pb[(size_t)N_NODES * F_IN];
__device__ float g_q[3][N_NODES];
__device__ float g_U[2][USZ];
__device__ __nv_bfloat16 g_Uhi[4 * USZ];
__device__ __nv_bfloat16 g_Ulo[4 * USZ];
__device__ float g_c[6][HID];                 // c21,c32,c43,c31,c42,c41
__device__ float g_H[(size_t)N_NODES * HCAT];

__device__ __forceinline__ float neg_inf() { return __int_as_float(0xff800000); }

// ---------------- low-level helpers ----------------------------------------
__device__ __forceinline__ uint32_t smem_u32(const void* p) {
    uint32_t a;
    asm("{ .reg .u64 t; cvta.to.shared.u64 t, %1; cvt.u32.u64 %0, t; }" : "=r"(a) : "l"(p));
    return a;
}
__device__ __forceinline__ void cpa16(uint32_t dst, const void* src, int sz) {
    asm volatile("cp.async.cg.shared.global [%0], [%1], 16, %2;"
                 :: "r"(dst), "l"(src), "r"(sz) : "memory");
}
__device__ __forceinline__ void ldsm4(uint32_t* r, uint32_t addr) {
    asm volatile("ldmatrix.sync.aligned.m8n8.x4.shared.b16 {%0,%1,%2,%3}, [%4];"
                 : "=r"(r[0]), "=r"(r[1]), "=r"(r[2]), "=r"(r[3]) : "r"(addr));
}
__device__ __forceinline__ void mma16816(float* c, const uint32_t* a, const uint32_t* b) {
    asm volatile("mma.sync.aligned.m16n8k16.row.col.f32.bf16.bf16.f32 "
                 "{%0,%1,%2,%3}, {%4,%5,%6,%7}, {%8,%9}, {%0,%1,%2,%3};"
                 : "+f"(c[0]), "+f"(c[1]), "+f"(c[2]), "+f"(c[3])
                 : "r"(a[0]), "r"(a[1]), "r"(a[2]), "r"(a[3]), "r"(b[0]), "r"(b[1]));
}
__device__ __forceinline__ uint32_t pack2(__nv_bfloat16 a, __nv_bfloat16 b) {
    return (uint32_t)__bfloat16_as_ushort(a) | ((uint32_t)__bfloat16_as_ushort(b) << 16);
}
__device__ __forceinline__ uint32_t phys(int row, int c16) {
    uint32_t line = (uint32_t)(row >> 1);
    uint32_t c8 = (uint32_t)(((row & 1) << 2) | c16) ^ (line & 7u);
    return line * 128u + c8 * 16u;
}
__device__ __forceinline__ void split1(float v, __nv_bfloat16& h, __nv_bfloat16& l) {
    h = __float2bfloat16_rn(v);
    l = __float2bfloat16_rn(v - __bfloat162float(h));
}

// ---------------- graph preprocessing --------------------------------------
__global__ void k_init() {
    int i = blockIdx.x * blockDim.x + threadIdx.x;
    if (i < N_NODES) { g_deg[i] = 1.0f; g_cnt[i] = 0; g_cursor[i] = 0; }
    if (i < N_GRAPHS) g_gcount[i] = 0;
}

__global__ void k_count(const int* __restrict__ ei, const int* __restrict__ batch) {
    int i = blockIdx.x * blockDim.x + threadIdx.x;
    if (i < N_EDGES) {
        int d = ei[N_EDGES + i];
        atomicAdd(&g_deg[d], 1.0f);
        atomicAdd(&g_cnt[d], 1);
    }
    if (i < N_NODES) atomicAdd(&g_gcount[batch[i]], 1);
}

// block 0: row scan (int4, exactly 500 threads x 40) + dis; block 1: graph scan
__global__ void k_scan2() {
    int t = threadIdx.x;
    if (blockIdx.x == 0) {
        __shared__ int part[512];
        int base = t * 40;
        int loc[40];
        int s = 0;
        if (t < 500) {
#pragma unroll
            for (int j = 0; j < 10; j++) {
                int4 v = *(const int4*)&g_cnt[base + j * 4];
                loc[j * 4 + 0] = v.x; loc[j * 4 + 1] = v.y;
                loc[j * 4 + 2] = v.z; loc[j * 4 + 3] = v.w;
                s += v.x + v.y + v.z + v.w;
                float4 d = *(const float4*)&g_deg[base + j * 4];
                float4 r = make_float4(rsqrtf(d.x), rsqrtf(d.y), rsqrtf(d.z), rsqrtf(d.w));
                *(float4*)&g_dis[base + j * 4] = r;
            }
        }
        part[t] = s;
        __syncthreads();
        for (int off = 1; off < 512; off <<= 1) {
            int v = (t >= off) ? part[t - off] : 0;
            __syncthreads();
            part[t] += v;
            __syncthreads();
        }
        if (t < 500) {
            int run = (t == 0) ? 0 : part[t - 1];
#pragma unroll
            for (int j = 0; j < 40; j++) { g_rowstart[base + j] = run; run += loc[j]; }
        }
        if (t == 511) g_rowstart[N_NODES] = part[511];
    } else {
        __shared__ int sh[N_GRAPHS];
        if (t < N_GRAPHS) sh[t] = g_gcount[t];
        __syncthreads();
        for (int off = 1; off < N_GRAPHS; off <<= 1) {
            int v = (t >= off && t < N_GRAPHS) ? sh[t - off] : 0;
            __syncthreads();
            if (t < N_GRAPHS) sh[t] += v;
            __syncthreads();
        }
        if (t < N_GRAPHS) g_gstart[t + 1] = sh[t];
        if (t == 0) g_gstart[0] = 0;
    }
}

__global__ void k_edges_fill(const int* __restrict__ ei) {
    int e = blockIdx.x * blockDim.x + threadIdx.x;
    if (e >= N_EDGES) return;
    int s = ei[e];
    int d = ei[N_EDGES + e];
    int p = g_rowstart[d] + atomicAdd(&g_cursor[d], 1);
    g_csr_src[p] = s;
    g_csr_w[p] = g_dis[s] * g_dis[d];
}

// ---------------- merged weight/bias chain ----------------------------------
__device__ void wprod_body(const float* __restrict__ Wb, const float* __restrict__ Uin,
                           float* __restrict__ Uout, int split_idx, int wb,
                           float (*As)[33], float (*Bs)[33]) {
    int t = threadIdx.x;
    int tx = t & 15, ty = t >> 4;
    int m0 = (wb >> 2) * 32, n0 = (wb & 3) * 32;
    float acc[2][2] = {{0.f, 0.f}, {0.f, 0.f}};
    for (int k0 = 0; k0 < HID; k0 += 32) {
#pragma unroll
        for (int j = 0; j < 4; j++) {
            int idx = t + j * 256;
            int r = idx >> 5, cc = idx & 31;
            As[r][cc] = Wb[(size_t)(m0 + r) * HID + k0 + cc];
            Bs[r][cc] = Uin[(size_t)(k0 + r) * F_IN + n0 + cc];
        }
        __syncthreads();
#pragma unroll
        for (int kk = 0; kk < 32; kk++) {
            float a0 = As[ty * 2][kk], a1 = As[ty * 2 + 1][kk];
            float b0 = Bs[kk][tx * 2], b1 = Bs[kk][tx * 2 + 1];
            acc[0][0] += a0 * b0; acc[0][1] += a0 * b1;
            acc[1][0] += a1 * b0; acc[1][1] += a1 * b1;
        }
        __syncthreads();
    }
#pragma unroll
    for (int i = 0; i < 2; i++)
#pragma unroll
        for (int j = 0; j < 2; j++) {
            int m = m0 + ty * 2 + i, n = n0 + tx * 2 + j;
            float v = acc[i][j];
            Uout[(size_t)m * F_IN + n] = v;
            __nv_bfloat16 h, l;
            split1(v, h, l);
            g_Uhi[(size_t)split_idx * USZ + (size_t)m * F_IN + n] = h;
            g_Ulo[(size_t)split_idx * USZ + (size_t)m * F_IN + n] = l;
        }
}

__device__ void matvec_body(const float* __restrict__ W, const float* __restrict__ v,
                            int i, int out_idx, float* red) {
    int t = threadIdx.x;
    float p = 0.f;
    for (int j = t; j < HID; j += 256) p += W[(size_t)i * HID + j] * v[j];
    red[t] = p;
    __syncthreads();
    for (int off = 128; off > 0; off >>= 1) {
        if (t < off) red[t] += red[t + off];
        __syncthreads();
    }
    if (t == 0) g_c[out_idx][i] = red[0];
}

__global__ void k_wchain1(const float* __restrict__ W1, const float* __restrict__ W2,
                          const float* __restrict__ W3, const float* __restrict__ W4,
                          const float* __restrict__ b1, const float* __restrict__ b2,
                          const float* __restrict__ b3) {
    __shared__ float As[32][33], Bs[32][33];
    __shared__ float red[256];
    int bx = blockIdx.x;
    if (bx < 64) {
        int id = bx * 256 + threadIdx.x;   // < 16384
        float4 v = *(const float4*)(W1 + (size_t)id * 4);
        __nv_bfloat16 h0, h1, h2, h3, l0, l1, l2, l3;
        split1(v.x, h0, l0); split1(v.y, h1, l1); split1(v.z, h2, l2); split1(v.w, h3, l3);
        ((uint2*)g_Uhi)[id] = make_uint2(pack2(h0, h1), pack2(h2, h3));
        ((uint2*)g_Ulo)[id] = make_uint2(pack2(l0, l1), pack2(l2, l3));
    }
    else if (bx < 128) wprod_body(W2, W1, g_U[0], 1, bx - 64, As, Bs);
    else if (bx < 640)  matvec_body(W2, b1, bx - 128, 0, red);
    else if (bx < 1152) matvec_body(W3, b2, bx - 640, 1, red);
    else                matvec_body(W4, b3, bx - 1152, 2, red);
}

__global__ void k_wchain2(const float* __restrict__ W3, const float* __restrict__ W4) {
    __shared__ float As[32][33], Bs[32][33];
    __shared__ float red[256];
    int bx = blockIdx.x;
    if (bx < 64)       wprod_body(W3, g_U[0], g_U[1], 2, bx, As, Bs);
    else if (bx < 576) matvec_body(W3, g_c[0], bx - 64, 3, red);    // c31 = W3 c21
    else               matvec_body(W4, g_c[1], bx - 576, 4, red);   // c42 = W4 c32
}

__global__ void k_wchain3(const float* __restrict__ W4) {
    __shared__ float As[32][33], Bs[32][33];
    __shared__ float red[256];
    int bx = blockIdx.x;
    if (bx < 64) wprod_body(W4, g_U[1], g_U[0], 3, bx, As, Bs);
    else         matvec_body(W4, g_c[3], bx - 64, 5, red);          // c41 = W4 c31
}

// ---------------- fused layer: gather (SpMM) + split + GEMM + epilogue -----
// CTA = one 128-row m-block. A (hi/lo, K=128) resident in smem (4 chunks of
// stride 8208 each to stagger banks); B streamed per n-block in 32-K chunks,
// double buffered. 256 threads, 8 warps, warp tile 64x32.
#define A_CH_STRIDE 8208u
#define A_REGION (4u * A_CH_STRIDE)          // 32832
#define B_OFF (2u * A_REGION)                // 65664
#define SMB_L (B_OFF + 2u * 16384u + 1024u)  // 99456

__global__ void __launch_bounds__(256, 2) k_layer(int layer,
                                                  const float* __restrict__ xin,
                                                  const float* __restrict__ bias) {
    extern __shared__ char smraw[];
    uint32_t sb = smem_u32(smraw);
    uint32_t base = (sb + 1023u) & ~1023u;

    int t = threadIdx.x, lane = t & 31, w = t >> 5;
    int wm = (w & 1) * 64, wn = (w >> 1) * 32;
    int m0 = blockIdx.x * 128;

    const float* Pin = (layer == 0) ? xin : ((layer & 1) ? g_Pa : g_Pb);
    float* Pout = (layer & 1) ? g_Pb : g_Pa;
    const float* qin = (layer == 0) ? nullptr : g_q[layer - 1];
    const __nv_bfloat16* Bhi = g_Uhi + (size_t)layer * USZ;
    const __nv_bfloat16* Blo = g_Ulo + (size_t)layer * USZ;

    // --- B chunk issue: n-block nb, K-chunk ci -> buffer bsel ---
    auto issueB = [&](int nb, int ci, int bsel) {
        int k0 = ci * 32;
        uint32_t bufb = base + B_OFF + (uint32_t)bsel * 16384u;
#pragma unroll
        for (int j = 0; j < 2; j++) {
            int id = t + j * 256;
            int row = id >> 2, c16 = id & 3;
            uint32_t off = phys(row, c16);
            const __nv_bfloat16* sh = Bhi + (size_t)(nb * 128 + row) * F_IN + k0 + c16 * 8;
            const __nv_bfloat16* sl = Blo + (size_t)(nb * 128 + row) * F_IN + k0 + c16 * 8;
            cpa16(bufb + off, sh, 16);
            cpa16(bufb + 8192u + off, sl, 16);
        }
    };

    issueB(0, 0, 0);
    asm volatile("cp.async.commit_group;" ::: "memory");

    // --- prologue: CSR gather of 16 rows per warp; deposit bf16 hi/lo in smem
    {
        int kc = lane >> 3;
        int c16 = (lane & 7) >> 1;
        uint32_t sub = (uint32_t)(lane & 1) * 8u;
        const float4* __restrict__ Pi4 = (const float4*)Pin;
#pragma unroll 1
        for (int i = 0; i < 16; i++) {
            int rl = w + 8 * i;            // local row 0..127
            int rg = m0 + rl;
            float4 acc = make_float4(0.f, 0.f, 0.f, 0.f);
            float qacc = 0.f;
            if (rg < N_NODES) {
                float dii = g_dis[rg];
                float sw = dii * dii;
                float4 v = Pi4[(size_t)rg * 32 + lane];
                acc = make_float4(sw * v.x, sw * v.y, sw * v.z, sw * v.w);
                qacc = sw * (qin ? qin[rg] : 1.0f);
                int e = g_rowstart[rg], e1 = g_rowstart[rg + 1];
                for (; e < e1; e++) {
                    int s = g_csr_src[e];
                    float ww = g_csr_w[e];
                    float4 u = Pi4[(size_t)s * 32 + lane];
                    acc.x += ww * u.x; acc.y += ww * u.y;
                    acc.z += ww * u.z; acc.w += ww * u.w;
                    if (layer < 3) qacc += ww * (qin ? qin[s] : 1.0f);
                }
                if (layer < 3) {
                    ((float4*)Pout)[(size_t)rg * 32 + lane] = acc;
                    if (lane == 0) g_q[layer][rg] = qacc;
                }
            }
            __nv_bfloat16 h0, h1, h2, h3, l0, l1, l2, l3;
            split1(acc.x, h0, l0); split1(acc.y, h1, l1);
            split1(acc.z, h2, l2); split1(acc.w, h3, l3);
            uint32_t ap = base + (uint32_t)kc * A_CH_STRIDE + phys(rl, c16) + sub;
            *(uint2*)(smraw + (ap - sb)) = make_uint2(pack2(h0, h1), pack2(h2, h3));
            *(uint2*)(smraw + (ap + A_REGION - sb)) = make_uint2(pack2(l0, l1), pack2(l2, l3));
        }
    }
    __syncthreads();

    int lrow = (lane & 7) | (((lane >> 3) & 1) << 3);
    int lc = lane >> 4;
    int er = lane >> 2, ec = (lane & 3) * 2;

    // rank-1 terms for epilogue
    const float* qp[3] = {nullptr, nullptr, nullptr};
    const float* ep[3] = {nullptr, nullptr, nullptr};
    int nterm = layer;
    if (layer == 1)      { qp[0] = g_q[0]; ep[0] = g_c[0]; }
    else if (layer == 2) { qp[0] = g_q[1]; ep[0] = g_c[3]; qp[1] = g_q[0]; ep[1] = g_c[1]; }
    else if (layer == 3) { qp[0] = g_q[2]; ep[0] = g_c[5]; qp[1] = g_q[1]; ep[1] = g_c[4];
                           qp[2] = g_q[0]; ep[2] = g_c[2]; }
    int coloff = layer * HID;

    for (int nb = 0; nb < 4; nb++) {
        if (nb > 0) {
            issueB(nb, 0, 0);
            asm volatile("cp.async.commit_group;" ::: "memory");
        }
        float c[4][4][4];
#pragma unroll
        for (int i = 0; i < 4; i++)
#pragma unroll
            for (int j = 0; j < 4; j++)
#pragma unroll
                for (int r = 0; r < 4; r++) c[i][j][r] = 0.0f;

        for (int ci = 0; ci < 4; ci++) {
            if (ci < 3) {
                issueB(nb, ci + 1, (ci + 1) & 1);
                asm volatile("cp.async.commit_group;" ::: "memory");
                asm volatile("cp.async.wait_group 1;" ::: "memory");
            } else {
                asm volatile("cp.async.wait_group 0;" ::: "memory");
            }
            __syncthreads();

            uint32_t bbuf = base + B_OFF + (uint32_t)(ci & 1) * 16384u;
            uint32_t abuf = base + (uint32_t)ci * A_CH_STRIDE;
#pragma unroll
            for (int s = 0; s < 2; s++) {
                uint32_t bh[4][2], bl[4][2];
#pragma unroll
                for (int p = 0; p < 2; p++) {
                    uint32_t off = phys(wn + p * 16 + lrow, s * 2 + lc);
                    uint32_t r[4];
                    ldsm4(r, bbuf + off);
                    bh[2 * p][0] = r[0]; bh[2 * p + 1][0] = r[1];
                    bh[2 * p][1] = r[2]; bh[2 * p + 1][1] = r[3];
                    ldsm4(r, bbuf + 8192u + off);
                    bl[2 * p][0] = r[0]; bl[2 * p + 1][0] = r[1];
                    bl[2 * p][1] = r[2]; bl[2 * p + 1][1] = r[3];
                }
#pragma unroll
                for (int mt = 0; mt < 4; mt++) {
                    uint32_t ah[4], al[4];
                    uint32_t off = phys(wm + mt * 16 + lrow, s * 2 + lc);
                    ldsm4(ah, abuf + off);
                    ldsm4(al, abuf + A_REGION + off);
#pragma unroll
                    for (int nt = 0; nt < 4; nt++) {
                        mma16816(c[mt][nt], ah, bh[nt]);
                        mma16816(c[mt][nt], ah, bl[nt]);
                        mma16816(c[mt][nt], al, bh[nt]);
                    }
                }
            }
            __syncthreads();
        }

        // epilogue for this n-block
        int n0 = nb * 128;
#pragma unroll
        for (int mt = 0; mt < 4; mt++) {
            int r0 = m0 + wm + mt * 16 + er;
            int r1 = r0 + 8;
            float q0[3] = {0.f, 0.f, 0.f}, q1[3] = {0.f, 0.f, 0.f};
            for (int tt = 0; tt < nterm; tt++) {
                if (r0 < N_NODES) q0[tt] = qp[tt][r0];
                if (r1 < N_NODES) q1[tt] = qp[tt][r1];
            }
#pragma unroll
            for (int nt = 0; nt < 4; nt++) {
                int col = n0 + wn + nt * 8 + ec;
                float b0 = bias[col], b1v = bias[col + 1];
                float v00 = c[mt][nt][0] + b0, v01 = c[mt][nt][1] + b1v;
                float v10 = c[mt][nt][2] + b0, v11 = c[mt][nt][3] + b1v;
                for (int tt = 0; tt < nterm; tt++) {
                    float e0 = ep[tt][col], e1 = ep[tt][col + 1];
                    v00 += q0[tt] * e0; v01 += q0[tt] * e1;
                    v10 += q1[tt] * e0; v11 += q1[tt] * e1;
                }
                if (r0 < N_NODES)
                    *(float2*)&g_H[(size_t)r0 * HCAT + coloff + col] = make_float2(v00, v01);
                if (r1 < N_NODES)
                    *(float2*)&g_H[(size_t)r1 * HCAT + coloff + col] = make_float2(v10, v11);
            }
        }
    }
}

// ---------------- pooling: out = [segmax(H), segmean(H>0)] -----------------
__global__ void k_pool(float* __restrict__ out) {
    int col = blockIdx.x * blockDim.x + threadIdx.x;
    int g   = blockIdx.y;
    int i0 = g_gstart[g], i1 = g_gstart[g + 1];
    float mx = neg_inf();
    float pos = 0.0f;
    for (int i = i0; i < i1; i++) {
        float v = g_H[(size_t)i * HCAT + col];
        mx = fmaxf(mx, v);
        pos += (v > 0.0f) ? 1.0f : 0.0f;
    }
    int cnt = i1 - i0;
    out[(size_t)g * (2 * HCAT) + col] = mx;
    out[(size_t)g * (2 * HCAT) + HCAT + col] = (cnt > 0) ? pos / (float)cnt : 0.0f;
}

// ---------------- launch ----------------------------------------------------
extern "C" void kernel_launch(void* const* d_in, const int* in_sizes, int n_in,
                              void* d_out, int out_size) {
    const float* x     = (const float*)d_in[0];
    const int*   ei    = (const int*)d_in[1];
    const int*   batch = (const int*)d_in[2];
    // d_in[3]=lin_W, d_in[4]=lin_b : dead code in reference
    const float* W1 = (const float*)d_in[5];  const float* b1 = (const float*)d_in[6];
    const float* W2 = (const float*)d_in[7];  const float* b2 = (const float*)d_in[8];
    const float* W3 = (const float*)d_in[9];  const float* b3 = (const float*)d_in[10];
    const float* W4 = (const float*)d_in[11]; const float* b4 = (const float*)d_in[12];
    float* out = (float*)d_out;

    cudaFuncSetAttribute(k_layer, cudaFuncAttributeMaxDynamicSharedMemorySize, SMB_L);

    k_init<<<(N_NODES + 255) / 256, 256>>>();
    k_count<<<(N_EDGES + 255) / 256, 256>>>(ei, batch);
    k_scan2<<<2, 512>>>();
    k_edges_fill<<<(N_EDGES + 255) / 256, 256>>>(ei);

    k_wchain1<<<1664, 256>>>(W1, W2, W3, W4, b1, b2, b3);
    k_wchain2<<<1088, 256>>>(W3, W4);
    k_wchain3<<<576, 256>>>(W4);

    int mgrid = (N_NODES + 127) / 128;   // 157
    k_layer<<<mgrid, 256, SMB_L>>>(0, x, b1);
    k_layer<<<mgrid, 256, SMB_L>>>(1, x, b2);
    k_layer<<<mgrid, 256, SMB_L>>>(2, x, b3);
    k_layer<<<mgrid, 256, SMB_L>>>(3, x, b4);

    dim3 pgrid(HCAT / 256, N_GRAPHS);
    k_pool<<<pgrid, 256>>>(out);
}